// round 1
// baseline (speedup 1.0000x reference)
#include <cuda_runtime.h>
#include <cstdint>

// FP16 pulse (16 floats of 0.0/1.0 per element) -> FP8 E4M3 pulse (8 floats).
// Pure streaming kernel: 1.074 GB in, 0.537 GB out, no reuse -> HBM-bound.
// One thread per element: 4x LDG.128 in, branchless bit-level convert, 2x STG.128 out.

__device__ __forceinline__ unsigned BITU(unsigned u) {
    // input floats are exactly 0.0f (0x00000000) or 1.0f (0x3F800000);
    // bit 29 distinguishes them without a predicate
    return (u >> 29) & 1u;
}

__global__ void __launch_bounds__(256)
fp16_to_fp8_kernel(const uint4* __restrict__ in, uint4* __restrict__ out, int n) {
    int i = blockIdx.x * blockDim.x + threadIdx.x;
    if (i >= n) return;

    const uint4 w0 = in[4 * i + 0];
    const uint4 w1 = in[4 * i + 1];
    const uint4 w2 = in[4 * i + 2];
    const uint4 w3 = in[4 * i + 3];

    // ---- unpack: [S, E4..E0, M9..M0] MSB-first across the 16 words
    unsigned s = BITU(w0.x);
    unsigned e = (BITU(w0.y) << 4) | (BITU(w0.z) << 3) | (BITU(w0.w) << 2) |
                 (BITU(w1.x) << 1) |  BITU(w1.y);
    unsigned m = (BITU(w1.z) << 9) | (BITU(w1.w) << 8) |
                 (BITU(w2.x) << 7) | (BITU(w2.y) << 6) |
                 (BITU(w2.z) << 5) | (BITU(w2.w) << 4) |
                 (BITU(w3.x) << 3) | (BITU(w3.y) << 2) |
                 (BITU(w3.z) << 1) |  BITU(w3.w);

    // ---- normal path (fp16 exp field 9..22): RNE(m >> 7), carry bumps exponent
    unsigned keep = m >> 7;
    unsigned sticky_n = (m & 63u) ? 1u : 0u;
    unsigned up_n = ((m >> 6) & 1u) & (sticky_n | (keep & 1u));
    unsigned mr = keep + up_n;                       // 0..8
    unsigned norm = (((e - 8u) + (mr >> 3)) << 3) | (mr & 7u);  // packed E<<3|M

    // ---- subnormal/boundary path (fp16 exp field 5..8):
    // msub = RNE((1024+m) >> (16-e)); msub==8 promotes to E=1,M=0,
    // which is exactly the packed value 8 -> packed result is msub itself.
    unsigned x = 1024u + m;
    int kk_i = 16 - (int)e;
    unsigned kk = (unsigned)min(max(kk_i, 8), 11);   // matches jnp.clip; identity when selected
    unsigned keep2 = x >> kk;
    unsigned low = (1u << (kk - 1u)) - 1u;
    unsigned sticky_s = (x & low) ? 1u : 0u;
    unsigned up_s = ((x >> (kk - 1u)) & 1u) & (sticky_s | (keep2 & 1u));
    unsigned msub = keep2 + up_s;                    // packed E<<3|M directly

    // ---- select: ovf (e>22) -> E=15,M=6 (0x7E); unf (e<5) -> 0; sub (5..8); else normal
    unsigned em = (e > 22u) ? 0x7Eu
                : (e < 5u)  ? 0u
                : (e <= 8u) ? msub
                :             norm;
    unsigned R = (s << 7) | em;                      // 8-bit packed result

    // ---- expand to 8 floats: bit * 0x3F800000 (single IMAD per lane)
    const unsigned ONE = 0x3F800000u;
    uint4 o0, o1;
    o0.x = ((R >> 7) & 1u) * ONE;
    o0.y = ((R >> 6) & 1u) * ONE;
    o0.z = ((R >> 5) & 1u) * ONE;
    o0.w = ((R >> 4) & 1u) * ONE;
    o1.x = ((R >> 3) & 1u) * ONE;
    o1.y = ((R >> 2) & 1u) * ONE;
    o1.z = ((R >> 1) & 1u) * ONE;
    o1.w = ( R       & 1u) * ONE;

    out[2 * i]     = o0;
    out[2 * i + 1] = o1;
}

extern "C" void kernel_launch(void* const* d_in, const int* in_sizes, int n_in,
                              void* d_out, int out_size) {
    const uint4* in = (const uint4*)d_in[0];
    uint4* out = (uint4*)d_out;
    int n = in_sizes[0] / 16;                 // 16 input floats per element
    int threads = 256;
    int blocks = (n + threads - 1) / threads; // 16.7M / 256 = 65536 exactly
    fp16_to_fp8_kernel<<<blocks, threads>>>(in, out, n);
}